// round 1
// baseline (speedup 1.0000x reference)
#include <cuda_runtime.h>

#define T_TOK 4096      // B*S
#define D_DIM 1024
#define F_DIM 4096
#define E_NUM 8
#define A_TOT (T_TOK*2) // total assignments (top-2)

// ---------------- device scratch (static; no runtime allocation) -------------
__device__ int   g_route_e[A_TOT];
__device__ float g_route_p[A_TOT];
__device__ int   g_counts[E_NUM];
__device__ int   g_offsets[E_NUM];
__device__ int   g_fill[E_NUM];
__device__ int   g_tok[A_TOT];
__device__ float g_prob[A_TOT];
__device__ float g_h[(size_t)A_TOT * F_DIM];   // 128 MiB intermediate

// ---------------- tiny metadata kernels -------------------------------------
__global__ void zero_meta_kernel() {
    int i = threadIdx.x;
    if (i < E_NUM) { g_counts[i] = 0; g_fill[i] = 0; }
}

__global__ void scan_kernel() {
    if (threadIdx.x == 0) {
        int s = 0;
        #pragma unroll
        for (int e = 0; e < E_NUM; ++e) { g_offsets[e] = s; s += g_counts[e]; }
    }
}

__global__ void gather_kernel() {
    int t = blockIdx.x * blockDim.x + threadIdx.x;
    if (t >= T_TOK) return;
    #pragma unroll
    for (int j = 0; j < 2; ++j) {
        int e = g_route_e[2 * t + j];
        int pos = g_offsets[e] + atomicAdd(&g_fill[e], 1);
        g_tok[pos]  = t;
        g_prob[pos] = g_route_p[2 * t + j];
    }
}

__global__ void zero_out_kernel(float* out) {
    size_t i = (size_t)(blockIdx.x * blockDim.x + threadIdx.x) * 4;
    if (i < (size_t)T_TOK * D_DIM) {
        *(float4*)(out + i) = make_float4(0.f, 0.f, 0.f, 0.f);
    }
}

// ---------------- gating: logits, top-2, softmax -----------------------------
__global__ __launch_bounds__(256) void gate_kernel(
    const float* __restrict__ x, const float* __restrict__ Wg,
    const float* __restrict__ bg)
{
    __shared__ float sWgT[E_NUM * D_DIM];   // transposed: [e][d], 32 KB
    int tid = threadIdx.x;
    for (int i = tid; i < D_DIM * E_NUM; i += 256) {
        int d = i / E_NUM, e = i % E_NUM;
        sWgT[e * D_DIM + d] = Wg[i];
    }
    __syncthreads();

    int warp = tid >> 5, lane = tid & 31;
    int t = blockIdx.x * 8 + warp;
    if (t >= T_TOK) return;

    float acc[E_NUM];
    #pragma unroll
    for (int e = 0; e < E_NUM; ++e) acc[e] = 0.f;

    const float* xr = x + (size_t)t * D_DIM;
    #pragma unroll 4
    for (int it = 0; it < D_DIM / 32; ++it) {
        float xv = xr[it * 32 + lane];
        #pragma unroll
        for (int e = 0; e < E_NUM; ++e)
            acc[e] += xv * sWgT[e * D_DIM + it * 32 + lane];
    }
    #pragma unroll
    for (int off = 16; off > 0; off >>= 1)
        #pragma unroll
        for (int e = 0; e < E_NUM; ++e)
            acc[e] += __shfl_xor_sync(0xffffffffu, acc[e], off);

    if (lane == 0) {
        #pragma unroll
        for (int e = 0; e < E_NUM; ++e) acc[e] += bg[e];
        // top-2, jax tie-break (first index wins) via strict >
        int e0 = 0;
        #pragma unroll
        for (int e = 1; e < E_NUM; ++e) if (acc[e] > acc[e0]) e0 = e;
        int e1 = (e0 == 0) ? 1 : 0;
        #pragma unroll
        for (int e = 0; e < E_NUM; ++e)
            if (e != e0 && acc[e] > acc[e1]) e1 = e;
        float v0 = acc[e0], v1 = acc[e1];
        float p1 = 1.f / (1.f + __expf(v0 - v1));   // softmax over {v0,v1}
        float p0 = 1.f - p1;
        g_route_e[2 * t]     = e0;  g_route_p[2 * t]     = p0;
        g_route_e[2 * t + 1] = e1;  g_route_p[2 * t + 1] = p1;
        atomicAdd(&g_counts[e0], 1);
        atomicAdd(&g_counts[e1], 1);
    }
}

// ---------------- grouped GEMM1: h = relu(x_gathered @ W1[e] + b1[e]) -------
// BM=BN=128, BK=8, 256 threads, 8x8 per thread
__global__ __launch_bounds__(256) void gemm1_kernel(
    const float* __restrict__ x, const float* __restrict__ W1,
    const float* __restrict__ b1)
{
    int e  = blockIdx.y >> 5;
    int mt = blockIdx.y & 31;
    int cnt = g_counts[e];
    int row0 = mt * 128;
    if (row0 >= cnt) return;
    int base = g_offsets[e];
    int n0 = blockIdx.x * 128;

    __shared__ float As[8 * 128];
    __shared__ float Bs[8 * 128];

    int tid = threadIdx.x;
    int arow = tid >> 1;
    int acol = (tid & 1) * 4;
    int r = row0 + arow;
    const float* xrow = (r < cnt) ? (x + (size_t)g_tok[base + r] * D_DIM) : nullptr;

    int brow = tid >> 5;
    int bcol = (tid & 31) * 4;
    const float* Bg = W1 + (size_t)e * D_DIM * F_DIM + (size_t)brow * F_DIM + n0 + bcol;

    int tx = tid & 15, ty = tid >> 4;
    float acc[8][8];
    #pragma unroll
    for (int i = 0; i < 8; ++i)
        #pragma unroll
        for (int j = 0; j < 8; ++j) acc[i][j] = 0.f;

    for (int k0 = 0; k0 < D_DIM; k0 += 8) {
        float4 av = xrow ? *(const float4*)(xrow + k0 + acol)
                         : make_float4(0.f, 0.f, 0.f, 0.f);
        float4 bv = *(const float4*)(Bg + (size_t)k0 * F_DIM);
        __syncthreads();
        As[(acol + 0) * 128 + arow] = av.x;
        As[(acol + 1) * 128 + arow] = av.y;
        As[(acol + 2) * 128 + arow] = av.z;
        As[(acol + 3) * 128 + arow] = av.w;
        *(float4*)&Bs[brow * 128 + bcol] = bv;
        __syncthreads();
        #pragma unroll
        for (int kk = 0; kk < 8; ++kk) {
            float4 ra0 = *(float4*)&As[kk * 128 + ty * 8];
            float4 ra1 = *(float4*)&As[kk * 128 + ty * 8 + 4];
            float4 rb0 = *(float4*)&Bs[kk * 128 + tx * 8];
            float4 rb1 = *(float4*)&Bs[kk * 128 + tx * 8 + 4];
            float ra[8] = {ra0.x, ra0.y, ra0.z, ra0.w, ra1.x, ra1.y, ra1.z, ra1.w};
            float rb[8] = {rb0.x, rb0.y, rb0.z, rb0.w, rb1.x, rb1.y, rb1.z, rb1.w};
            #pragma unroll
            for (int i = 0; i < 8; ++i)
                #pragma unroll
                for (int j = 0; j < 8; ++j)
                    acc[i][j] += ra[i] * rb[j];
        }
    }

    const float* b1e = b1 + e * F_DIM + n0 + tx * 8;
    float bb[8];
    #pragma unroll
    for (int j = 0; j < 8; ++j) bb[j] = b1e[j];

    #pragma unroll
    for (int i = 0; i < 8; ++i) {
        int rr = row0 + ty * 8 + i;
        if (rr >= cnt) continue;
        float* hrow = g_h + (size_t)(base + rr) * F_DIM + n0 + tx * 8;
        float4 o0, o1;
        o0.x = fmaxf(acc[i][0] + bb[0], 0.f);
        o0.y = fmaxf(acc[i][1] + bb[1], 0.f);
        o0.z = fmaxf(acc[i][2] + bb[2], 0.f);
        o0.w = fmaxf(acc[i][3] + bb[3], 0.f);
        o1.x = fmaxf(acc[i][4] + bb[4], 0.f);
        o1.y = fmaxf(acc[i][5] + bb[5], 0.f);
        o1.z = fmaxf(acc[i][6] + bb[6], 0.f);
        o1.w = fmaxf(acc[i][7] + bb[7], 0.f);
        *(float4*)hrow = o0;
        *(float4*)(hrow + 4) = o1;
    }
}

// ---------------- grouped GEMM2: out += prob * (h @ W2[e] + b2[e]) ----------
__global__ __launch_bounds__(256) void gemm2_kernel(
    const float* __restrict__ W2, const float* __restrict__ b2,
    float* __restrict__ out)
{
    int e  = blockIdx.y >> 5;
    int mt = blockIdx.y & 31;
    int cnt = g_counts[e];
    int row0 = mt * 128;
    if (row0 >= cnt) return;
    int base = g_offsets[e];
    int n0 = blockIdx.x * 128;

    __shared__ float As[8 * 128];
    __shared__ float Bs[8 * 128];

    int tid = threadIdx.x;
    int arow = tid >> 1;
    int acol = (tid & 1) * 4;
    int r = row0 + arow;
    const float* hrowp = (r < cnt) ? (g_h + (size_t)(base + r) * F_DIM) : nullptr;

    int brow = tid >> 5;
    int bcol = (tid & 31) * 4;
    const float* Bg = W2 + (size_t)e * F_DIM * D_DIM + (size_t)brow * D_DIM + n0 + bcol;

    int tx = tid & 15, ty = tid >> 4;
    float acc[8][8];
    #pragma unroll
    for (int i = 0; i < 8; ++i)
        #pragma unroll
        for (int j = 0; j < 8; ++j) acc[i][j] = 0.f;

    for (int k0 = 0; k0 < F_DIM; k0 += 8) {
        float4 av = hrowp ? *(const float4*)(hrowp + k0 + acol)
                          : make_float4(0.f, 0.f, 0.f, 0.f);
        float4 bv = *(const float4*)(Bg + (size_t)k0 * D_DIM);
        __syncthreads();
        As[(acol + 0) * 128 + arow] = av.x;
        As[(acol + 1) * 128 + arow] = av.y;
        As[(acol + 2) * 128 + arow] = av.z;
        As[(acol + 3) * 128 + arow] = av.w;
        *(float4*)&Bs[brow * 128 + bcol] = bv;
        __syncthreads();
        #pragma unroll
        for (int kk = 0; kk < 8; ++kk) {
            float4 ra0 = *(float4*)&As[kk * 128 + ty * 8];
            float4 ra1 = *(float4*)&As[kk * 128 + ty * 8 + 4];
            float4 rb0 = *(float4*)&Bs[kk * 128 + tx * 8];
            float4 rb1 = *(float4*)&Bs[kk * 128 + tx * 8 + 4];
            float ra[8] = {ra0.x, ra0.y, ra0.z, ra0.w, ra1.x, ra1.y, ra1.z, ra1.w};
            float rb[8] = {rb0.x, rb0.y, rb0.z, rb0.w, rb1.x, rb1.y, rb1.z, rb1.w};
            #pragma unroll
            for (int i = 0; i < 8; ++i)
                #pragma unroll
                for (int j = 0; j < 8; ++j)
                    acc[i][j] += ra[i] * rb[j];
        }
    }

    const float* b2e = b2 + e * D_DIM + n0 + tx * 8;
    float bb[8];
    #pragma unroll
    for (int j = 0; j < 8; ++j) bb[j] = b2e[j];

    #pragma unroll
    for (int i = 0; i < 8; ++i) {
        int rr = row0 + ty * 8 + i;
        if (rr >= cnt) continue;
        int slot = base + rr;
        int tok  = g_tok[slot];
        float p  = g_prob[slot];
        float* orow = out + (size_t)tok * D_DIM + n0 + tx * 8;
        #pragma unroll
        for (int j = 0; j < 8; ++j)
            atomicAdd(&orow[j], p * (acc[i][j] + bb[j]));
    }
}

// ---------------- launch -----------------------------------------------------
extern "C" void kernel_launch(void* const* d_in, const int* in_sizes, int n_in,
                              void* d_out, int out_size)
{
    const float* x  = (const float*)d_in[0];
    const float* W1 = (const float*)d_in[1];
    const float* b1 = (const float*)d_in[2];
    const float* W2 = (const float*)d_in[3];
    const float* b2 = (const float*)d_in[4];
    const float* Wg = (const float*)d_in[5];
    const float* bg = (const float*)d_in[6];
    float* out = (float*)d_out;

    zero_meta_kernel<<<1, 32>>>();
    gate_kernel<<<T_TOK / 8, 256>>>(x, Wg, bg);
    scan_kernel<<<1, 32>>>();
    gather_kernel<<<T_TOK / 256, 256>>>();
    zero_out_kernel<<<(T_TOK * D_DIM / 4 + 255) / 256, 256>>>(out);

    dim3 g1(F_DIM / 128, E_NUM * 32);   // (32, 256)
    gemm1_kernel<<<g1, 256>>>(x, W1, b1);

    dim3 g2(D_DIM / 128, E_NUM * 32);   // (8, 256)
    gemm2_kernel<<<g2, 256>>>(W2, b2, out);
}

// round 2
// speedup vs baseline: 1.0017x; 1.0017x over previous
#include <cuda_runtime.h>

#define T_TOK 4096      // B*S
#define D_DIM 1024
#define F_DIM 4096
#define E_NUM 8
#define A_TOT (T_TOK*2) // total assignments (top-2)

// ---------------- device scratch (static; no runtime allocation) -------------
__device__ int   g_route_e[A_TOT];
__device__ float g_route_p[A_TOT];
__device__ int   g_counts[E_NUM];
__device__ int   g_offsets[E_NUM];
__device__ int   g_fill[E_NUM];
__device__ int   g_tok[A_TOT];
__device__ float g_prob[A_TOT];
__device__ float g_h[(size_t)A_TOT * F_DIM];   // 128 MiB intermediate

// ---------------- tiny metadata kernels -------------------------------------
__global__ void zero_meta_kernel() {
    int i = threadIdx.x;
    if (i < E_NUM) { g_counts[i] = 0; g_fill[i] = 0; }
}

__global__ void scan_kernel() {
    if (threadIdx.x == 0) {
        int s = 0;
        #pragma unroll
        for (int e = 0; e < E_NUM; ++e) { g_offsets[e] = s; s += g_counts[e]; }
    }
}

__global__ void gather_kernel() {
    int t = blockIdx.x * blockDim.x + threadIdx.x;
    if (t >= T_TOK) return;
    #pragma unroll
    for (int j = 0; j < 2; ++j) {
        int e = g_route_e[2 * t + j];
        int pos = g_offsets[e] + atomicAdd(&g_fill[e], 1);
        g_tok[pos]  = t;
        g_prob[pos] = g_route_p[2 * t + j];
    }
}

__global__ void zero_out_kernel(float* out) {
    size_t i = (size_t)(blockIdx.x * blockDim.x + threadIdx.x) * 4;
    if (i < (size_t)T_TOK * D_DIM) {
        *(float4*)(out + i) = make_float4(0.f, 0.f, 0.f, 0.f);
    }
}

// ---------------- gating: logits, top-2, softmax -----------------------------
__global__ __launch_bounds__(256) void gate_kernel(
    const float* __restrict__ x, const float* __restrict__ Wg,
    const float* __restrict__ bg)
{
    __shared__ float sWgT[E_NUM * D_DIM];   // transposed: [e][d], 32 KB
    int tid = threadIdx.x;
    for (int i = tid; i < D_DIM * E_NUM; i += 256) {
        int d = i / E_NUM, e = i % E_NUM;
        sWgT[e * D_DIM + d] = Wg[i];
    }
    __syncthreads();

    int warp = tid >> 5, lane = tid & 31;
    int t = blockIdx.x * 8 + warp;
    if (t >= T_TOK) return;

    float acc[E_NUM];
    #pragma unroll
    for (int e = 0; e < E_NUM; ++e) acc[e] = 0.f;

    const float* xr = x + (size_t)t * D_DIM;
    #pragma unroll 4
    for (int it = 0; it < D_DIM / 32; ++it) {
        float xv = xr[it * 32 + lane];
        #pragma unroll
        for (int e = 0; e < E_NUM; ++e)
            acc[e] += xv * sWgT[e * D_DIM + it * 32 + lane];
    }
    #pragma unroll
    for (int off = 16; off > 0; off >>= 1)
        #pragma unroll
        for (int e = 0; e < E_NUM; ++e)
            acc[e] += __shfl_xor_sync(0xffffffffu, acc[e], off);

    if (lane == 0) {
        #pragma unroll
        for (int e = 0; e < E_NUM; ++e) acc[e] += bg[e];
        // top-2, jax tie-break (first index wins) via strict >
        int e0 = 0;
        #pragma unroll
        for (int e = 1; e < E_NUM; ++e) if (acc[e] > acc[e0]) e0 = e;
        int e1 = (e0 == 0) ? 1 : 0;
        #pragma unroll
        for (int e = 0; e < E_NUM; ++e)
            if (e != e0 && acc[e] > acc[e1]) e1 = e;
        float v0 = acc[e0], v1 = acc[e1];
        float p1 = 1.f / (1.f + __expf(v0 - v1));   // softmax over {v0,v1}
        float p0 = 1.f - p1;
        g_route_e[2 * t]     = e0;  g_route_p[2 * t]     = p0;
        g_route_e[2 * t + 1] = e1;  g_route_p[2 * t + 1] = p1;
        atomicAdd(&g_counts[e0], 1);
        atomicAdd(&g_counts[e1], 1);
    }
}

// ---------------- grouped GEMM1: h = relu(x_gathered @ W1[e] + b1[e]) -------
// BM=BN=128, BK=8, 256 threads, 8x8 per thread
__global__ __launch_bounds__(256) void gemm1_kernel(
    const float* __restrict__ x, const float* __restrict__ W1,
    const float* __restrict__ b1)
{
    int e  = blockIdx.y >> 5;
    int mt = blockIdx.y & 31;
    int cnt = g_counts[e];
    int row0 = mt * 128;
    if (row0 >= cnt) return;
    int base = g_offsets[e];
    int n0 = blockIdx.x * 128;

    __shared__ float As[8 * 128];
    __shared__ float Bs[8 * 128];

    int tid = threadIdx.x;
    int arow = tid >> 1;
    int acol = (tid & 1) * 4;
    int r = row0 + arow;
    const float* xrow = (r < cnt) ? (x + (size_t)g_tok[base + r] * D_DIM) : nullptr;

    int brow = tid >> 5;
    int bcol = (tid & 31) * 4;
    const float* Bg = W1 + (size_t)e * D_DIM * F_DIM + (size_t)brow * F_DIM + n0 + bcol;

    int tx = tid & 15, ty = tid >> 4;
    float acc[8][8];
    #pragma unroll
    for (int i = 0; i < 8; ++i)
        #pragma unroll
        for (int j = 0; j < 8; ++j) acc[i][j] = 0.f;

    for (int k0 = 0; k0 < D_DIM; k0 += 8) {
        float4 av = xrow ? *(const float4*)(xrow + k0 + acol)
                         : make_float4(0.f, 0.f, 0.f, 0.f);
        float4 bv = *(const float4*)(Bg + (size_t)k0 * F_DIM);
        __syncthreads();
        As[(acol + 0) * 128 + arow] = av.x;
        As[(acol + 1) * 128 + arow] = av.y;
        As[(acol + 2) * 128 + arow] = av.z;
        As[(acol + 3) * 128 + arow] = av.w;
        *(float4*)&Bs[brow * 128 + bcol] = bv;
        __syncthreads();
        #pragma unroll
        for (int kk = 0; kk < 8; ++kk) {
            float4 ra0 = *(float4*)&As[kk * 128 + ty * 8];
            float4 ra1 = *(float4*)&As[kk * 128 + ty * 8 + 4];
            float4 rb0 = *(float4*)&Bs[kk * 128 + tx * 8];
            float4 rb1 = *(float4*)&Bs[kk * 128 + tx * 8 + 4];
            float ra[8] = {ra0.x, ra0.y, ra0.z, ra0.w, ra1.x, ra1.y, ra1.z, ra1.w};
            float rb[8] = {rb0.x, rb0.y, rb0.z, rb0.w, rb1.x, rb1.y, rb1.z, rb1.w};
            #pragma unroll
            for (int i = 0; i < 8; ++i)
                #pragma unroll
                for (int j = 0; j < 8; ++j)
                    acc[i][j] += ra[i] * rb[j];
        }
    }

    const float* b1e = b1 + e * F_DIM + n0 + tx * 8;
    float bb[8];
    #pragma unroll
    for (int j = 0; j < 8; ++j) bb[j] = b1e[j];

    #pragma unroll
    for (int i = 0; i < 8; ++i) {
        int rr = row0 + ty * 8 + i;
        if (rr >= cnt) continue;
        float* hrow = g_h + (size_t)(base + rr) * F_DIM + n0 + tx * 8;
        float4 o0, o1;
        o0.x = fmaxf(acc[i][0] + bb[0], 0.f);
        o0.y = fmaxf(acc[i][1] + bb[1], 0.f);
        o0.z = fmaxf(acc[i][2] + bb[2], 0.f);
        o0.w = fmaxf(acc[i][3] + bb[3], 0.f);
        o1.x = fmaxf(acc[i][4] + bb[4], 0.f);
        o1.y = fmaxf(acc[i][5] + bb[5], 0.f);
        o1.z = fmaxf(acc[i][6] + bb[6], 0.f);
        o1.w = fmaxf(acc[i][7] + bb[7], 0.f);
        *(float4*)hrow = o0;
        *(float4*)(hrow + 4) = o1;
    }
}

// ---------------- grouped GEMM2: out += prob * (h @ W2[e] + b2[e]) ----------
__global__ __launch_bounds__(256) void gemm2_kernel(
    const float* __restrict__ W2, const float* __restrict__ b2,
    float* __restrict__ out)
{
    int e  = blockIdx.y >> 5;
    int mt = blockIdx.y & 31;
    int cnt = g_counts[e];
    int row0 = mt * 128;
    if (row0 >= cnt) return;
    int base = g_offsets[e];
    int n0 = blockIdx.x * 128;

    __shared__ float As[8 * 128];
    __shared__ float Bs[8 * 128];

    int tid = threadIdx.x;
    int arow = tid >> 1;
    int acol = (tid & 1) * 4;
    int r = row0 + arow;
    const float* hrowp = (r < cnt) ? (g_h + (size_t)(base + r) * F_DIM) : nullptr;

    int brow = tid >> 5;
    int bcol = (tid & 31) * 4;
    const float* Bg = W2 + (size_t)e * F_DIM * D_DIM + (size_t)brow * D_DIM + n0 + bcol;

    int tx = tid & 15, ty = tid >> 4;
    float acc[8][8];
    #pragma unroll
    for (int i = 0; i < 8; ++i)
        #pragma unroll
        for (int j = 0; j < 8; ++j) acc[i][j] = 0.f;

    for (int k0 = 0; k0 < F_DIM; k0 += 8) {
        float4 av = hrowp ? *(const float4*)(hrowp + k0 + acol)
                          : make_float4(0.f, 0.f, 0.f, 0.f);
        float4 bv = *(const float4*)(Bg + (size_t)k0 * D_DIM);
        __syncthreads();
        As[(acol + 0) * 128 + arow] = av.x;
        As[(acol + 1) * 128 + arow] = av.y;
        As[(acol + 2) * 128 + arow] = av.z;
        As[(acol + 3) * 128 + arow] = av.w;
        *(float4*)&Bs[brow * 128 + bcol] = bv;
        __syncthreads();
        #pragma unroll
        for (int kk = 0; kk < 8; ++kk) {
            float4 ra0 = *(float4*)&As[kk * 128 + ty * 8];
            float4 ra1 = *(float4*)&As[kk * 128 + ty * 8 + 4];
            float4 rb0 = *(float4*)&Bs[kk * 128 + tx * 8];
            float4 rb1 = *(float4*)&Bs[kk * 128 + tx * 8 + 4];
            float ra[8] = {ra0.x, ra0.y, ra0.z, ra0.w, ra1.x, ra1.y, ra1.z, ra1.w};
            float rb[8] = {rb0.x, rb0.y, rb0.z, rb0.w, rb1.x, rb1.y, rb1.z, rb1.w};
            #pragma unroll
            for (int i = 0; i < 8; ++i)
                #pragma unroll
                for (int j = 0; j < 8; ++j)
                    acc[i][j] += ra[i] * rb[j];
        }
    }

    const float* b2e = b2 + e * D_DIM + n0 + tx * 8;
    float bb[8];
    #pragma unroll
    for (int j = 0; j < 8; ++j) bb[j] = b2e[j];

    #pragma unroll
    for (int i = 0; i < 8; ++i) {
        int rr = row0 + ty * 8 + i;
        if (rr >= cnt) continue;
        int slot = base + rr;
        int tok  = g_tok[slot];
        float p  = g_prob[slot];
        float* orow = out + (size_t)tok * D_DIM + n0 + tx * 8;
        #pragma unroll
        for (int j = 0; j < 8; ++j)
            atomicAdd(&orow[j], p * (acc[i][j] + bb[j]));
    }
}

// ---------------- launch -----------------------------------------------------
extern "C" void kernel_launch(void* const* d_in, const int* in_sizes, int n_in,
                              void* d_out, int out_size)
{
    const float* x  = (const float*)d_in[0];
    const float* W1 = (const float*)d_in[1];
    const float* b1 = (const float*)d_in[2];
    const float* W2 = (const float*)d_in[3];
    const float* b2 = (const float*)d_in[4];
    const float* Wg = (const float*)d_in[5];
    const float* bg = (const float*)d_in[6];
    float* out = (float*)d_out;

    zero_meta_kernel<<<1, 32>>>();
    gate_kernel<<<T_TOK / 8, 256>>>(x, Wg, bg);
    scan_kernel<<<1, 32>>>();
    gather_kernel<<<T_TOK / 256, 256>>>();
    zero_out_kernel<<<(T_TOK * D_DIM / 4 + 255) / 256, 256>>>(out);

    dim3 g1(F_DIM / 128, E_NUM * 32);   // (32, 256)
    gemm1_kernel<<<g1, 256>>>(x, W1, b1);

    dim3 g2(D_DIM / 128, E_NUM * 32);   // (8, 256)
    gemm2_kernel<<<g2, 256>>>(W2, b2, out);
}

// round 3
// speedup vs baseline: 1.2835x; 1.2813x over previous
#include <cuda_runtime.h>

#define T_TOK 4096      // B*S
#define D_DIM 1024
#define F_DIM 4096
#define E_NUM 8
#define A_TOT (T_TOK*2) // total assignments (top-2)

// tile geometry
#define AS_STRIDE 20            // 16 + 4 pad (conflict-free, 16B-aligned rows)
#define BS_STRIDE 132           // 128 + 4 pad
#define AS_SZ (128*AS_STRIDE)   // 2560 floats
#define BS_SZ (16*BS_STRIDE)    // 2112 floats
#define SMEM_FLOATS (4*AS_SZ + 4*BS_SZ)   // hi/lo x double-buffer = 18688 floats = 74752 B

// ---------------- device scratch (static; no runtime allocation) -------------
__device__ int   g_route_e[A_TOT];
__device__ float g_route_p[A_TOT];
__device__ int   g_counts[E_NUM];
__device__ int   g_offsets[E_NUM];
__device__ int   g_fill[E_NUM];
__device__ int   g_tok[A_TOT];
__device__ float g_prob[A_TOT];
__device__ float g_h[(size_t)A_TOT * F_DIM];   // 128 MiB intermediate

// ---------------- helpers -----------------------------------------------------
__device__ __forceinline__ float tf32_rn(float f) {
    unsigned u;
    asm("cvt.rna.tf32.f32 %0, %1;" : "=r"(u) : "f"(f));
    return __uint_as_float(u);
}

__device__ __forceinline__ void mma_tf32(float* c, const float* a, const float* b) {
    asm volatile(
        "mma.sync.aligned.m16n8k8.row.col.f32.tf32.tf32.f32 "
        "{%0,%1,%2,%3}, {%4,%5,%6,%7}, {%8,%9}, {%0,%1,%2,%3};"
        : "+f"(c[0]), "+f"(c[1]), "+f"(c[2]), "+f"(c[3])
        : "r"(__float_as_uint(a[0])), "r"(__float_as_uint(a[1])),
          "r"(__float_as_uint(a[2])), "r"(__float_as_uint(a[3])),
          "r"(__float_as_uint(b[0])), "r"(__float_as_uint(b[1])));
}

__device__ __forceinline__ void split4(float4 v, float4& h, float4& l) {
    h.x = tf32_rn(v.x); l.x = tf32_rn(v.x - h.x);
    h.y = tf32_rn(v.y); l.y = tf32_rn(v.y - h.y);
    h.z = tf32_rn(v.z); l.z = tf32_rn(v.z - h.z);
    h.w = tf32_rn(v.w); l.w = tf32_rn(v.w - h.w);
}

// ---------------- tiny metadata kernels -------------------------------------
__global__ void zero_meta_kernel() {
    int i = threadIdx.x;
    if (i < E_NUM) { g_counts[i] = 0; g_fill[i] = 0; }
}

__global__ void scan_kernel() {
    if (threadIdx.x == 0) {
        int s = 0;
        #pragma unroll
        for (int e = 0; e < E_NUM; ++e) { g_offsets[e] = s; s += g_counts[e]; }
    }
}

__global__ void gather_kernel() {
    int t = blockIdx.x * blockDim.x + threadIdx.x;
    if (t >= T_TOK) return;
    #pragma unroll
    for (int j = 0; j < 2; ++j) {
        int e = g_route_e[2 * t + j];
        int pos = g_offsets[e] + atomicAdd(&g_fill[e], 1);
        g_tok[pos]  = t;
        g_prob[pos] = g_route_p[2 * t + j];
    }
}

__global__ void zero_out_kernel(float* out) {
    size_t i = (size_t)(blockIdx.x * blockDim.x + threadIdx.x) * 4;
    if (i < (size_t)T_TOK * D_DIM) {
        *(float4*)(out + i) = make_float4(0.f, 0.f, 0.f, 0.f);
    }
}

// ---------------- gating: logits, top-2, softmax -----------------------------
__global__ __launch_bounds__(256) void gate_kernel(
    const float* __restrict__ x, const float* __restrict__ Wg,
    const float* __restrict__ bg)
{
    __shared__ float sWgT[E_NUM * D_DIM];   // transposed: [e][d], 32 KB
    int tid = threadIdx.x;
    for (int i = tid; i < D_DIM * E_NUM; i += 256) {
        int d = i / E_NUM, e = i % E_NUM;
        sWgT[e * D_DIM + d] = Wg[i];
    }
    __syncthreads();

    int warp = tid >> 5, lane = tid & 31;
    int t = blockIdx.x * 8 + warp;
    if (t >= T_TOK) return;

    float acc[E_NUM];
    #pragma unroll
    for (int e = 0; e < E_NUM; ++e) acc[e] = 0.f;

    const float* xr = x + (size_t)t * D_DIM;
    #pragma unroll 4
    for (int it = 0; it < D_DIM / 32; ++it) {
        float xv = xr[it * 32 + lane];
        #pragma unroll
        for (int e = 0; e < E_NUM; ++e)
            acc[e] += xv * sWgT[e * D_DIM + it * 32 + lane];
    }
    #pragma unroll
    for (int off = 16; off > 0; off >>= 1)
        #pragma unroll
        for (int e = 0; e < E_NUM; ++e)
            acc[e] += __shfl_xor_sync(0xffffffffu, acc[e], off);

    if (lane == 0) {
        #pragma unroll
        for (int e = 0; e < E_NUM; ++e) acc[e] += bg[e];
        int e0 = 0;
        #pragma unroll
        for (int e = 1; e < E_NUM; ++e) if (acc[e] > acc[e0]) e0 = e;
        int e1 = (e0 == 0) ? 1 : 0;
        #pragma unroll
        for (int e = 0; e < E_NUM; ++e)
            if (e != e0 && acc[e] > acc[e1]) e1 = e;
        float v0 = acc[e0], v1 = acc[e1];
        float p1 = 1.f / (1.f + __expf(v0 - v1));
        float p0 = 1.f - p1;
        g_route_e[2 * t]     = e0;  g_route_p[2 * t]     = p0;
        g_route_e[2 * t + 1] = e1;  g_route_p[2 * t + 1] = p1;
        atomicAdd(&g_counts[e0], 1);
        atomicAdd(&g_counts[e1], 1);
    }
}

// ============ tensor-core mainloop shared by both GEMMs (macro body) =========
// BM=128 BN=128 BK=16, 256 threads, 8 warps in 2x4, warp tile 64x32.
// 3xTF32: smem holds hi and lo tiles (split once at store time).

#define GEMM_COMPUTE_BUF(buf)                                                   \
    {                                                                           \
        const int aoff = (buf) * AS_SZ;                                         \
        const int boff = (buf) * BS_SZ;                                         \
        _Pragma("unroll")                                                       \
        for (int kst = 0; kst < 2; ++kst) {                                     \
            int kb = kst * 8;                                                   \
            float ahi[4][4], alo[4][4], bhi[4][2], blo[4][2];                   \
            int ra = (lane >> 2), ca = kb + (lane & 3);                         \
            _Pragma("unroll")                                                   \
            for (int mi = 0; mi < 4; ++mi) {                                    \
                int m = wm * 64 + mi * 16 + ra;                                 \
                const float* ph = AsHi + aoff + m * AS_STRIDE;                  \
                const float* pl = AsLo + aoff + m * AS_STRIDE;                  \
                ahi[mi][0] = ph[ca];                                            \
                ahi[mi][1] = ph[8 * AS_STRIDE + ca];                            \
                ahi[mi][2] = ph[ca + 4];                                        \
                ahi[mi][3] = ph[8 * AS_STRIDE + ca + 4];                        \
                alo[mi][0] = pl[ca];                                            \
                alo[mi][1] = pl[8 * AS_STRIDE + ca];                            \
                alo[mi][2] = pl[ca + 4];                                        \
                alo[mi][3] = pl[8 * AS_STRIDE + ca + 4];                        \
            }                                                                   \
            _Pragma("unroll")                                                   \
            for (int ni = 0; ni < 4; ++ni) {                                    \
                int n  = wn * 32 + ni * 8 + (lane >> 2);                        \
                int kk = kb + (lane & 3);                                       \
                bhi[ni][0] = BsHi[boff + kk * BS_STRIDE + n];                   \
                bhi[ni][1] = BsHi[boff + (kk + 4) * BS_STRIDE + n];             \
                blo[ni][0] = BsLo[boff + kk * BS_STRIDE + n];                   \
                blo[ni][1] = BsLo[boff + (kk + 4) * BS_STRIDE + n];             \
            }                                                                   \
            _Pragma("unroll")                                                   \
            for (int ni = 0; ni < 4; ++ni)                                      \
                _Pragma("unroll")                                               \
                for (int mi = 0; mi < 4; ++mi) {                                \
                    mma_tf32(acc[mi][ni], ahi[mi], blo[ni]);                    \
                    mma_tf32(acc[mi][ni], alo[mi], bhi[ni]);                    \
                    mma_tf32(acc[mi][ni], ahi[mi], bhi[ni]);                    \
                }                                                               \
        }                                                                       \
    }

#define GEMM_STORE_TILES(buf)                                                   \
    {                                                                           \
        float4 h, l;                                                            \
        float* dst;                                                             \
        split4(fa0, h, l);                                                      \
        dst = AsHi + (buf) * AS_SZ + ar * AS_STRIDE + ac; *(float4*)dst = h;    \
        dst = AsLo + (buf) * AS_SZ + ar * AS_STRIDE + ac; *(float4*)dst = l;    \
        split4(fa1, h, l);                                                      \
        dst = AsHi + (buf) * AS_SZ + (ar + 64) * AS_STRIDE + ac; *(float4*)dst = h; \
        dst = AsLo + (buf) * AS_SZ + (ar + 64) * AS_STRIDE + ac; *(float4*)dst = l; \
        split4(fb0, h, l);                                                      \
        dst = BsHi + (buf) * BS_SZ + bk * BS_STRIDE + bn; *(float4*)dst = h;    \
        dst = BsLo + (buf) * BS_SZ + bk * BS_STRIDE + bn; *(float4*)dst = l;    \
        split4(fb1, h, l);                                                      \
        dst = BsHi + (buf) * BS_SZ + (bk + 8) * BS_STRIDE + bn; *(float4*)dst = h; \
        dst = BsLo + (buf) * BS_SZ + (bk + 8) * BS_STRIDE + bn; *(float4*)dst = l; \
    }

// ---------------- grouped GEMM1: h = relu(x_gathered @ W1[e] + b1[e]) -------
__global__ __launch_bounds__(256) void gemm1_kernel(
    const float* __restrict__ x, const float* __restrict__ W1,
    const float* __restrict__ b1)
{
    extern __shared__ float sm[];
    float* AsHi = sm;
    float* AsLo = sm + 2 * AS_SZ;
    float* BsHi = sm + 4 * AS_SZ;
    float* BsLo = BsHi + 2 * BS_SZ;

    int e  = blockIdx.y >> 5;
    int mt = blockIdx.y & 31;
    int cnt = g_counts[e];
    int row0 = mt * 128;
    if (row0 >= cnt) return;
    int base = g_offsets[e];
    int n0 = blockIdx.x * 128;

    int tid = threadIdx.x;
    int lane = tid & 31, warp = tid >> 5;
    int wm = warp >> 2, wn = warp & 3;

    // A (gathered x rows) ldg mapping: two float4 per thread per iter
    int ar = tid >> 2;            // 0..63
    int ac = (tid & 3) * 4;       // k within tile
    int rr0 = row0 + ar, rr1 = rr0 + 64;
    const float* ap0 = (rr0 < cnt) ? x + (size_t)g_tok[base + rr0] * D_DIM : nullptr;
    const float* ap1 = (rr1 < cnt) ? x + (size_t)g_tok[base + rr1] * D_DIM : nullptr;
    // B (W1) ldg mapping
    int bk = tid >> 5;            // 0..7
    int bn = (tid & 31) * 4;
    const float* bp = W1 + (size_t)e * D_DIM * F_DIM + (size_t)bk * F_DIM + n0 + bn;

    float acc[4][4][4];
    #pragma unroll
    for (int a = 0; a < 4; ++a)
        #pragma unroll
        for (int b = 0; b < 4; ++b)
            #pragma unroll
            for (int c = 0; c < 4; ++c) acc[a][b][c] = 0.f;

    const int NIT = D_DIM / 16;
    float4 fa0, fa1, fb0, fb1;
    fa0 = ap0 ? *(const float4*)(ap0 + ac) : make_float4(0, 0, 0, 0);
    fa1 = ap1 ? *(const float4*)(ap1 + ac) : make_float4(0, 0, 0, 0);
    fb0 = *(const float4*)(bp);
    fb1 = *(const float4*)(bp + 8 * F_DIM);
    GEMM_STORE_TILES(0);

    for (int it = 0; it < NIT; ++it) {
        __syncthreads();
        int buf = it & 1;
        if (it + 1 < NIT) {
            int k0 = (it + 1) * 16;
            fa0 = ap0 ? *(const float4*)(ap0 + k0 + ac) : make_float4(0, 0, 0, 0);
            fa1 = ap1 ? *(const float4*)(ap1 + k0 + ac) : make_float4(0, 0, 0, 0);
            fb0 = *(const float4*)(bp + (size_t)k0 * F_DIM);
            fb1 = *(const float4*)(bp + (size_t)(k0 + 8) * F_DIM);
        }
        GEMM_COMPUTE_BUF(buf);
        if (it + 1 < NIT) GEMM_STORE_TILES(buf ^ 1);
    }

    // epilogue: bias + relu -> g_h
    const float* b1e = b1 + e * F_DIM + n0;
    #pragma unroll
    for (int ni = 0; ni < 4; ++ni) {
        int c = wn * 32 + ni * 8 + (lane & 3) * 2;
        float bb0 = b1e[c], bb1 = b1e[c + 1];
        #pragma unroll
        for (int mi = 0; mi < 4; ++mi) {
            int r = row0 + wm * 64 + mi * 16 + (lane >> 2);
            if (r < cnt) {
                float2 v;
                v.x = fmaxf(acc[mi][ni][0] + bb0, 0.f);
                v.y = fmaxf(acc[mi][ni][1] + bb1, 0.f);
                *(float2*)(g_h + (size_t)(base + r) * F_DIM + n0 + c) = v;
            }
            if (r + 8 < cnt) {
                float2 v;
                v.x = fmaxf(acc[mi][ni][2] + bb0, 0.f);
                v.y = fmaxf(acc[mi][ni][3] + bb1, 0.f);
                *(float2*)(g_h + (size_t)(base + r + 8) * F_DIM + n0 + c) = v;
            }
        }
    }
}

// ---------------- grouped GEMM2: out += prob * (h @ W2[e] + b2[e]) ----------
__global__ __launch_bounds__(256) void gemm2_kernel(
    const float* __restrict__ W2, const float* __restrict__ b2,
    float* __restrict__ out)
{
    extern __shared__ float sm[];
    float* AsHi = sm;
    float* AsLo = sm + 2 * AS_SZ;
    float* BsHi = sm + 4 * AS_SZ;
    float* BsLo = BsHi + 2 * BS_SZ;

    int e  = blockIdx.y >> 5;
    int mt = blockIdx.y & 31;
    int cnt = g_counts[e];
    int row0 = mt * 128;
    if (row0 >= cnt) return;
    int base = g_offsets[e];
    int n0 = blockIdx.x * 128;

    int tid = threadIdx.x;
    int lane = tid & 31, warp = tid >> 5;
    int wm = warp >> 2, wn = warp & 3;

    int ar = tid >> 2;
    int ac = (tid & 3) * 4;
    int rr0 = row0 + ar, rr1 = rr0 + 64;
    const float* ap0 = (rr0 < cnt) ? g_h + (size_t)(base + rr0) * F_DIM : nullptr;
    const float* ap1 = (rr1 < cnt) ? g_h + (size_t)(base + rr1) * F_DIM : nullptr;
    int bk = tid >> 5;
    int bn = (tid & 31) * 4;
    const float* bp = W2 + (size_t)e * F_DIM * D_DIM + (size_t)bk * D_DIM + n0 + bn;

    float acc[4][4][4];
    #pragma unroll
    for (int a = 0; a < 4; ++a)
        #pragma unroll
        for (int b = 0; b < 4; ++b)
            #pragma unroll
            for (int c = 0; c < 4; ++c) acc[a][b][c] = 0.f;

    const int NIT = F_DIM / 16;
    float4 fa0, fa1, fb0, fb1;
    fa0 = ap0 ? *(const float4*)(ap0 + ac) : make_float4(0, 0, 0, 0);
    fa1 = ap1 ? *(const float4*)(ap1 + ac) : make_float4(0, 0, 0, 0);
    fb0 = *(const float4*)(bp);
    fb1 = *(const float4*)(bp + 8 * D_DIM);
    GEMM_STORE_TILES(0);

    for (int it = 0; it < NIT; ++it) {
        __syncthreads();
        int buf = it & 1;
        if (it + 1 < NIT) {
            int k0 = (it + 1) * 16;
            fa0 = ap0 ? *(const float4*)(ap0 + k0 + ac) : make_float4(0, 0, 0, 0);
            fa1 = ap1 ? *(const float4*)(ap1 + k0 + ac) : make_float4(0, 0, 0, 0);
            fb0 = *(const float4*)(bp + (size_t)k0 * D_DIM);
            fb1 = *(const float4*)(bp + (size_t)(k0 + 8) * D_DIM);
        }
        GEMM_COMPUTE_BUF(buf);
        if (it + 1 < NIT) GEMM_STORE_TILES(buf ^ 1);
    }

    // epilogue: scale by prob, scatter-add into out
    const float* b2e = b2 + e * D_DIM + n0;
    #pragma unroll
    for (int mi = 0; mi < 4; ++mi) {
        int r = row0 + wm * 64 + mi * 16 + (lane >> 2);
        int   tok0 = -1, tok1 = -1;
        float p0 = 0.f, p1 = 0.f;
        if (r < cnt)     { tok0 = g_tok[base + r];     p0 = g_prob[base + r]; }
        if (r + 8 < cnt) { tok1 = g_tok[base + r + 8]; p1 = g_prob[base + r + 8]; }
        #pragma unroll
        for (int ni = 0; ni < 4; ++ni) {
            int c = wn * 32 + ni * 8 + (lane & 3) * 2;
            float bb0 = b2e[c], bb1 = b2e[c + 1];
            if (tok0 >= 0) {
                float* o = out + (size_t)tok0 * D_DIM + n0 + c;
                atomicAdd(o,     p0 * (acc[mi][ni][0] + bb0));
                atomicAdd(o + 1, p0 * (acc[mi][ni][1] + bb1));
            }
            if (tok1 >= 0) {
                float* o = out + (size_t)tok1 * D_DIM + n0 + c;
                atomicAdd(o,     p1 * (acc[mi][ni][2] + bb0));
                atomicAdd(o + 1, p1 * (acc[mi][ni][3] + bb1));
            }
        }
    }
}

// ---------------- launch -----------------------------------------------------
extern "C" void kernel_launch(void* const* d_in, const int* in_sizes, int n_in,
                              void* d_out, int out_size)
{
    const float* x  = (const float*)d_in[0];
    const float* W1 = (const float*)d_in[1];
    const float* b1 = (const float*)d_in[2];
    const float* W2 = (const float*)d_in[3];
    const float* b2 = (const float*)d_in[4];
    const float* Wg = (const float*)d_in[5];
    const float* bg = (const float*)d_in[6];
    float* out = (float*)d_out;

    size_t smem_bytes = (size_t)SMEM_FLOATS * sizeof(float);   // 74752 B
    cudaFuncSetAttribute(gemm1_kernel, cudaFuncAttributeMaxDynamicSharedMemorySize,
                         (int)smem_bytes);
    cudaFuncSetAttribute(gemm2_kernel, cudaFuncAttributeMaxDynamicSharedMemorySize,
                         (int)smem_bytes);

    zero_meta_kernel<<<1, 32>>>();
    gate_kernel<<<T_TOK / 8, 256>>>(x, Wg, bg);
    scan_kernel<<<1, 32>>>();
    gather_kernel<<<T_TOK / 256, 256>>>();
    zero_out_kernel<<<(T_TOK * D_DIM / 4 + 255) / 256, 256>>>(out);

    dim3 g1(F_DIM / 128, E_NUM * 32);   // (32, 256)
    gemm1_kernel<<<g1, 256, smem_bytes>>>(x, W1, b1);

    dim3 g2(D_DIM / 128, E_NUM * 32);   // (8, 256)
    gemm2_kernel<<<g2, 256, smem_bytes>>>(W2, b2, out);
}

// round 6
// speedup vs baseline: 2.2733x; 1.7712x over previous
#include <cuda_runtime.h>
#include <cuda_bf16.h>

#define T_TOK 4096
#define D_DIM 1024
#define F_DIM 4096
#define E_NUM 8
#define A_TOT (T_TOK*2)

#define SA_BYTES 80
#define SB_BYTES 272
#define ASZB (128*SA_BYTES)
#define BSZB (32*SB_BYTES)
#define SMEM_TOTAL_B (4*ASZB + 4*BSZB)

// ---------------- device scratch ---------------------------------------------
__device__ int   g_route_e[A_TOT];
__device__ float g_route_p[A_TOT];
__device__ int   g_counts[E_NUM];
__device__ int   g_offsets[E_NUM];
__device__ int   g_fill[E_NUM];
__device__ int   g_tok[A_TOT];
__device__ float g_prob[A_TOT];
__device__ float g_h[(size_t)A_TOT * F_DIM];

// ---------------- helpers -----------------------------------------------------
__device__ __forceinline__ void split2(float a, float b, unsigned& h, unsigned& l) {
    __nv_bfloat162 hv = __floats2bfloat162_rn(a, b);
    float2 hf = __bfloat1622float2(hv);
    __nv_bfloat162 lv = __floats2bfloat162_rn(a - hf.x, b - hf.y);
    h = *(unsigned*)&hv;
    l = *(unsigned*)&lv;
}

__device__ __forceinline__ void mma_bf16(float* c, const unsigned* a, const unsigned* b) {
    asm volatile(
        "mma.sync.aligned.m16n8k16.row.col.f32.bf16.bf16.f32 "
        "{%0,%1,%2,%3}, {%4,%5,%6,%7}, {%8,%9}, {%0,%1,%2,%3};"
        : "+f"(c[0]), "+f"(c[1]), "+f"(c[2]), "+f"(c[3])
        : "r"(a[0]), "r"(a[1]), "r"(a[2]), "r"(a[3]), "r"(b[0]), "r"(b[1]));
}

__device__ __forceinline__ void ldsm_x4(unsigned* r, unsigned addr) {
    asm volatile("ldmatrix.sync.aligned.m8n8.x4.shared.b16 {%0,%1,%2,%3}, [%4];"
                 : "=r"(r[0]), "=r"(r[1]), "=r"(r[2]), "=r"(r[3]) : "r"(addr));
}

__device__ __forceinline__ void ldsm_x2_trans(unsigned* r, unsigned addr) {
    asm volatile("ldmatrix.sync.aligned.m8n8.x2.trans.shared.b16 {%0,%1}, [%2];"
                 : "=r"(r[0]), "=r"(r[1]) : "r"(addr));
}

// ---- mainloop pieces ----------------------------------------------------------
__device__ __forceinline__ void gemm_compute(
    unsigned aB, unsigned bB, float (*acc)[4][4])
{
    #pragma unroll
    for (int kst = 0; kst < 2; ++kst) {
        const int kb = kst * 16;
        unsigned ah[4][4], al[4][4], bh[4][2], bl[4][2];
        #pragma unroll
        for (int mi = 0; mi < 4; ++mi) {
            unsigned ad = aB + mi * (16 * SA_BYTES) + kb * 2;
            ldsm_x4(ah[mi], ad);
            ldsm_x4(al[mi], ad + 2 * ASZB);
        }
        #pragma unroll
        for (int ni = 0; ni < 4; ++ni) {
            unsigned bd = bB + kb * SB_BYTES + ni * 16;
            ldsm_x2_trans(bh[ni], bd);
            ldsm_x2_trans(bl[ni], bd + 2 * BSZB);
        }
        #pragma unroll
        for (int ni = 0; ni < 4; ++ni) {
            #pragma unroll
            for (int mi = 0; mi < 4; ++mi) {
                mma_bf16(acc[mi][ni], ah[mi], bl[ni]);
                mma_bf16(acc[mi][ni], al[mi], bh[ni]);
                mma_bf16(acc[mi][ni], ah[mi], bh[ni]);
            }
        }
    }
}

__device__ __forceinline__ void gemm_store_tiles(
    char* sm, int buf, int awr, int awc, int bwr, int bwc,
    const float4* fa, const float4* fb)
{
    #pragma unroll
    for (int j = 0; j < 4; ++j) {
        unsigned h0, h1, l0, l1;
        split2(fa[j].x, fa[j].y, h0, l0);
        split2(fa[j].z, fa[j].w, h1, l1);
        char* d = sm + buf * ASZB + awr * SA_BYTES + (awc + j * 4) * 2;
        *(uint2*)d = make_uint2(h0, h1);
        *(uint2*)(d + 2 * ASZB) = make_uint2(l0, l1);
    }
    #pragma unroll
    for (int j = 0; j < 4; ++j) {
        unsigned h0, h1, l0, l1;
        split2(fb[j].x, fb[j].y, h0, l0);
        split2(fb[j].z, fb[j].w, h1, l1);
        char* d = sm + 4 * ASZB + buf * BSZB + bwr * SB_BYTES + (bwc + j * 4) * 2;
        *(uint2*)d = make_uint2(h0, h1);
        *(uint2*)(d + 2 * BSZB) = make_uint2(l0, l1);
    }
}

// ---------------- tiny metadata kernels -------------------------------------
__global__ void zero_meta_kernel() {
    int i = threadIdx.x;
    if (i < E_NUM) { g_counts[i] = 0; g_fill[i] = 0; }
}

__global__ void scan_kernel() {
    if (threadIdx.x == 0) {
        int s = 0;
        for (int e = 0; e < E_NUM; ++e) { g_offsets[e] = s; s += g_counts[e]; }
    }
}

__global__ void gather_kernel() {
    int t = blockIdx.x * blockDim.x + threadIdx.x;
    if (t >= T_TOK) return;
    for (int j = 0; j < 2; ++j) {
        int e = g_route_e[2 * t + j];
        int pos = g_offsets[e] + atomicAdd(&g_fill[e], 1);
        g_tok[pos]  = t;
        g_prob[pos] = g_route_p[2 * t + j];
    }
}

__global__ void zero_out_kernel(float* out) {
    size_t i = (size_t)(blockIdx.x * blockDim.x + threadIdx.x) * 4;
    if (i < (size_t)T_TOK * D_DIM) {
        *(float4*)(out + i) = make_float4(0.f, 0.f, 0.f, 0.f);
    }
}

// ---------------- gating: logits, top-2, softmax -----------------------------
__global__ __launch_bounds__(256) void gate_kernel(
    const float* __restrict__ x, const float* __restrict__ Wg,
    const float* __restrict__ bg)
{
    __shared__ float sWgT[E_NUM * D_DIM];
    int tid = threadIdx.x;
    for (int i = tid; i < D_DIM * E_NUM; i += 256) {
        int d = i / E_NUM, e = i % E_NUM;
        sWgT[e * D_DIM + d] = Wg[i];
    }
    __syncthreads();

    int warp = tid / 32, lane = tid % 32;
    int t = blockIdx.x * 8 + warp;
    if (t >= T_TOK) return;

    float acc[E_NUM];
    #pragma unroll
    for (int e = 0; e < E_NUM; ++e) { acc[e] = 0.f; }

    const float* xr = x + (size_t)t * D_DIM;
    #pragma unroll 4
    for (int it = 0; it < D_DIM / 32; ++it) {
        float xv = xr[it * 32 + lane];
        #pragma unroll
        for (int e = 0; e < E_NUM; ++e) {
            acc[e] += xv * sWgT[e * D_DIM + it * 32 + lane];
        }
    }
    #pragma unroll
    for (int off = 16; off > 0; off /= 2) {
        #pragma unroll
        for (int e = 0; e < E_NUM; ++e) {
            acc[e] += __shfl_xor_sync(0xffffffffu, acc[e], off);
        }
    }

    if (lane == 0) {
        #pragma unroll
        for (int e = 0; e < E_NUM; ++e) { acc[e] += bg[e]; }
        int e0 = 0;
        #pragma unroll
        for (int e = 1; e < E_NUM; ++e) { if (acc[e] > acc[e0]) e0 = e; }
        int e1 = (e0 == 0) ? 1 : 0;
        #pragma unroll
        for (int e = 0; e < E_NUM; ++e) {
            if (e != e0 && acc[e] > acc[e1]) e1 = e;
        }
        float v0 = acc[e0], v1 = acc[e1];
        float p1 = 1.f / (1.f + __expf(v0 - v1));
        float p0 = 1.f - p1;
        g_route_e[2 * t]     = e0;  g_route_p[2 * t]     = p0;
        g_route_e[2 * t + 1] = e1;  g_route_p[2 * t + 1] = p1;
        atomicAdd(&g_counts[e0], 1);
        atomicAdd(&g_counts[e1], 1);
    }
}

// ---------------- grouped GEMM1: h = relu(x_gathered @ W1[e] + b1[e]) -------
__global__ __launch_bounds__(256) void gemm1_kernel(
    const float* __restrict__ x, const float* __restrict__ W1,
    const float* __restrict__ b1)
{
    extern __shared__ char sm[];

    int e  = blockIdx.y / 32;
    int mt = blockIdx.y % 32;
    int cnt = g_counts[e];
    int row0 = mt * 128;
    if (row0 >= cnt) return;
    int base = g_offsets[e];
    int n0 = blockIdx.x * 128;

    int tid = threadIdx.x;
    int lane = tid % 32, warp = tid / 32;
    int wm = warp / 4, wn = warp % 4;

    unsigned sbase = (unsigned)__cvta_generic_to_shared(sm);
    unsigned aAddrL = sbase + (wm * 64 + (lane & 15)) * SA_BYTES + (lane & 16);
    unsigned bAddrL = sbase + 4 * ASZB + (lane & 15) * SB_BYTES + wn * 64;

    int awr = tid / 2;
    int awc = (tid % 2) * 16;
    int rr = row0 + awr;
    const float* ap = (rr < cnt) ? x + (size_t)g_tok[base + rr] * D_DIM : 0;

    int bwr = tid / 8;
    int bwc = (tid % 8) * 16;
    const float* bp = W1 + (size_t)e * D_DIM * F_DIM + (size_t)bwr * F_DIM + n0 + bwc;

    float acc[4][4][4];
    #pragma unroll
    for (int a = 0; a < 4; ++a) {
        #pragma unroll
        for (int b = 0; b < 4; ++b) {
            #pragma unroll
            for (int c = 0; c < 4; ++c) { acc[a][b][c] = 0.f; }
        }
    }

    const int NIT = D_DIM / 32;
    float4 fa[4], fb[4];
    #pragma unroll
    for (int j = 0; j < 4; ++j) {
        fa[j] = ap ? *(const float4*)(ap + awc + j * 4) : make_float4(0.f, 0.f, 0.f, 0.f);
        fb[j] = *(const float4*)(bp + j * 4);
    }
    gemm_store_tiles(sm, 0, awr, awc, bwr, bwc, fa, fb);

    for (int it = 0; it < NIT; ++it) {
        __syncthreads();
        int buf = it % 2;
        if (it + 1 < NIT) {
            int k0 = (it + 1) * 32;
            #pragma unroll
            for (int j = 0; j < 4; ++j) {
                fa[j] = ap ? *(const float4*)(ap + k0 + awc + j * 4)
                           : make_float4(0.f, 0.f, 0.f, 0.f);
                fb[j] = *(const float4*)(bp + (size_t)k0 * F_DIM + j * 4);
            }
        }
        gemm_compute(aAddrL + buf * ASZB, bAddrL + buf * BSZB, acc);
        if (it + 1 < NIT) {
            gemm_store_tiles(sm, 1 - buf, awr, awc, bwr, bwc, fa, fb);
        }
    }

    const float* b1e = b1 + e * F_DIM + n0;
    #pragma unroll
    for (int ni = 0; ni < 4; ++ni) {
        int c = wn * 32 + ni * 8 + (lane % 4) * 2;
        float bb0 = b1e[c], bb1 = b1e[c + 1];
        #pragma unroll
        for (int mi = 0; mi < 4; ++mi) {
            int r = row0 + wm * 64 + mi * 16 + lane / 4;
            if (r < cnt) {
                float2 v;
                v.x = fmaxf(acc[mi][ni][0] + bb0, 0.f);
                v.y = fmaxf(acc[mi][ni][1] + bb1, 0.f);
                *(float2*)(g_h + (size_t)(base + r) * F_DIM + n0 + c) = v;
            }
            if (r + 8 < cnt) {
                float2 v;
                v.x = fmaxf(acc[mi][ni][2] + bb0, 0.f);
                v.y = fmaxf(acc[mi][ni][3] + bb1, 0.f);
                *(float2*)(g_h + (size_t)(base + r + 8) * F_DIM + n0 + c) = v;
            }
        }
    }
}

// ---------------- grouped GEMM2: out += prob * (h @ W2[e] + b2[e]) ----------
__global__ __launch_bounds__(256) void gemm2_kernel(
    const float* __restrict__ W2, const float* __restrict__ b2,
    float* __restrict__ out)
{
    extern __shared__ char sm[];

    int e  = blockIdx.y / 32;
    int mt = blockIdx.y % 32;
    int cnt = g_counts[e];
    int row0 = mt * 128;
    if (row0 >= cnt) return;
    int base = g_offsets[e];
    int n0 = blockIdx.x * 128;

    int tid = threadIdx.x;
    int lane = tid % 32, warp = tid / 32;
    int wm = warp / 4, wn = warp % 4;

    unsigned sbase = (unsigned)__cvta_generic_to_shared(sm);
    unsigned aAddrL = sbase + (wm * 64 + (lane & 15)) * SA_BYTES + (lane & 16);
    unsigned bAddrL = sbase + 4 * ASZB + (lane & 15) * SB_BYTES + wn * 64;

    int awr = tid / 2;
    int awc = (tid % 2) * 16;
    int rr = row0 + awr;
    const float* ap = (rr < cnt) ? g_h + (size_t)(base + rr) * F_DIM : 0;

    int bwr = tid / 8;
    int bwc = (tid % 8) * 16;
    const float* bp = W2 + (size_t)e * F_DIM * D_DIM + (size_t)bwr * D_DIM + n0 + bwc;

    float acc[4][4][4];
    #pragma unroll
    for (int a = 0; a < 4; ++a) {
        #pragma unroll
        for (int b = 0; b < 4; ++b) {
            #pragma unroll
            for (int c = 0; c < 4; ++c) { acc[a][b][c] = 0.f; }
        }
    }

    const int NIT = F_DIM / 32;
    float4 fa[4], fb[4];
    #pragma unroll
    for (int j = 0; j < 4; ++j) {
        fa[j] = ap ? *(const float4*)(ap + awc + j * 4) : make_float4(0.f, 0.f, 0.f, 0.f);
        fb[j] = *(const float4*)(bp + j * 4);
    }
    gemm_store_tiles(sm, 0, awr, awc, bwr, bwc, fa, fb);

    for (int it = 0; it < NIT; ++it) {
        __syncthreads();
        int buf = it % 2;
        if (it + 1 < NIT) {
            int k0 = (it + 1) * 32;
            #pragma unroll
            for (int j = 0; j < 4; ++j) {
                fa[j] = ap ? *(const float4*)(ap + k0 + awc + j * 4)
                           : make_float4(0.f, 0.f, 0.f, 0.f);
                fb[j] = *(const float4*)(bp + (size_t)k0 * D_DIM + j * 4);
            }
        }
        gemm_compute(aAddrL + buf * ASZB, bAddrL + buf * BSZB, acc);
        if (it + 1 < NIT) {
            gemm_store_tiles(sm, 1 - buf, awr, awc, bwr, bwc, fa, fb);
        }
    }

    const float* b2e = b2 + e * D_DIM + n0;
    #pragma unroll
    for (int mi = 0; mi < 4; ++mi) {
        int r = row0 + wm * 64 + mi * 16 + lane / 4;
        int   tok0 = -1, tok1 = -1;
        float p0 = 0.f, p1 = 0.f;
        if (r < cnt)     { tok0 = g_tok[base + r];     p0 = g_prob[base + r]; }
        if (r + 8 < cnt) { tok1 = g_tok[base + r + 8]; p1 = g_prob[base + r + 8]; }
        #pragma unroll
        for (int ni = 0; ni < 4; ++ni) {
            int c = wn * 32 + ni * 8 + (lane % 4) * 2;
            float bb0 = b2e[c], bb1 = b2e[c + 1];
            if (tok0 >= 0) {
                float* o = out + (size_t)tok0 * D_DIM + n0 + c;
                atomicAdd(o,     p0 * (acc[mi][ni][0] + bb0));
                atomicAdd(o + 1, p0 * (acc[mi][ni][1] + bb1));
            }
            if (tok1 >= 0) {
                float* o = out + (size_t)tok1 * D_DIM + n0 + c;
                atomicAdd(o,     p1 * (acc[mi][ni][2] + bb0));
                atomicAdd(o + 1, p1 * (acc[mi][ni][3] + bb1));
            }
        }
    }
}

// ---------------- launch -----------------------------------------------------
extern "C" void kernel_launch(void* const* d_in, const int* in_sizes, int n_in,
                              void* d_out, int out_size)
{
    const float* x  = (const float*)d_in[0];
    const float* W1 = (const float*)d_in[1];
    const float* b1 = (const float*)d_in[2];
    const float* W2 = (const float*)d_in[3];
    const float* b2 = (const float*)d_in[4];
    const float* Wg = (const float*)d_in[5];
    const float* bg = (const float*)d_in[6];
    float* out = (float*)d_out;

    size_t smem_bytes = SMEM_TOTAL_B;
    cudaFuncSetAttribute(gemm1_kernel, cudaFuncAttributeMaxDynamicSharedMemorySize,
                         (int)smem_bytes);
    cudaFuncSetAttribute(gemm2_kernel, cudaFuncAttributeMaxDynamicSharedMemorySize,
                         (int)smem_bytes);

    zero_meta_kernel<<<1, 32>>>();
    gate_kernel<<<T_TOK / 8, 256>>>(x, Wg, bg);
    scan_kernel<<<1, 32>>>();
    gather_kernel<<<T_TOK / 256, 256>>>();
    zero_out_kernel<<<(T_TOK * D_DIM / 4 + 255) / 256, 256>>>(out);

    dim3 g1(F_DIM / 128, E_NUM * 32);
    gemm1_kernel<<<g1, 256, smem_bytes>>>(x, W1, b1);

    dim3 g2(D_DIM / 128, E_NUM * 32);
    gemm2_kernel<<<g2, 256, smem_bytes>>>(W2, b2, out);
}